// round 5
// baseline (speedup 1.0000x reference)
#include <cuda_runtime.h>

// ---------------------------------------------------------------------------
// MultitaskSNN round 5: scalar, 1 batch/thread (as round 3 = 233us), but
// weights moved from SMEM to __constant__ memory. Weight reads become
// LDCU -> uniform registers (separate port, floor 1/SMSP) instead of LDS
// through the L1 crossbar, which round 3/4 saturated at ~84%.
// Pipeline per launch: gather kernel packs inputs into a __device__ staging
// array; one D2D cudaMemcpyToSymbolAsync fills the constant bank; main kernel
// runs. All graph-capturable, no allocations. Arithmetic bit-exact vs ref.
// ---------------------------------------------------------------------------

#define TT 50
#define NIN 32
#define NSH 28
#define NCH 8
#define NCO 3
#define NRH 14

// constant-bank float offsets (16B-aligned row bases)
#define OW_SH 0        // 28*32 = 896
#define OB_SH 896      // 28
#define OW_CH 924      // 8*28 = 224
#define OB_CH 1148     // 8
#define OW_CO 1156     // 3*8 = 24
#define OB_CO 1180     // 3
#define OW_RH 1184     // 14*28 = 392
#define OB_RH 1576     // 14
#define OW_RO 1592     // 14
#define OB_RO 1606     // 1
#define SW_TOTAL 1608

#define THREADS 224

__constant__ __align__(16) float cw[SW_TOTAL];
__device__   __align__(16) float g_staging[SW_TOTAL];

// pack the 11 input arrays into staging with the layout above
__global__ void gather_kernel(
    const float* __restrict__ Wsh, const float* __restrict__ bsh,
    const float* __restrict__ Wch, const float* __restrict__ bch,
    const float* __restrict__ Wco, const float* __restrict__ bco,
    const float* __restrict__ Wrh, const float* __restrict__ brh,
    const float* __restrict__ Wro, const float* __restrict__ bro)
{
    const int i = threadIdx.x + blockIdx.x * blockDim.x;
    if (i >= SW_TOTAL) return;
    float v = 0.0f;
    if      (i < OB_SH)      v = Wsh[i - OW_SH];
    else if (i < OW_CH)      v = bsh[i - OB_SH];
    else if (i < OB_CH)      v = Wch[i - OW_CH];
    else if (i < OW_CO)      v = bch[i - OB_CH];
    else if (i < OB_CO)      v = Wco[i - OW_CO];
    else if (i < OB_CO + 3)  v = bco[i - OB_CO];
    else if (i < OW_RH)      v = 0.0f;           // pad
    else if (i < OB_RH)      v = Wrh[i - OW_RH];
    else if (i < OW_RO)      v = brh[i - OB_RH];
    else if (i < OB_RO)      v = Wro[i - OW_RO];
    else if (i == OB_RO)     v = bro[0];
    g_staging[i] = v;
}

// LIF (snntorch Leaky, reset='subtract'), rounding matches the reference:
//   reset = (m_prev > 1);  m = fma(0.9, m_prev, cur) - reset;  spk = (m > 1)
__device__ __forceinline__ float lif(float& m, float cur) {
    float r = (m > 1.0f) ? 1.0f : 0.0f;
    m = __fmaf_rn(0.9f, m, cur) - r;
    return (m > 1.0f) ? 1.0f : 0.0f;
}

// ascending-i dot over 28 spikes; weight indices are compile-time constants
// so reads come from the constant bank (LDCU/UR path).
template <int WOFF>
__device__ __forceinline__ float dot28c(const float* __restrict__ sps, int row) {
    float a = 0.0f;
#pragma unroll
    for (int i = 0; i < NSH; i++)
        a = __fmaf_rn(sps[i], cw[WOFF + row * NSH + i], a);
    return a;
}

__global__ __launch_bounds__(THREADS, 1) void snn_kernel(
    const float* __restrict__ x, float* __restrict__ out, int B)
{
    const int b = blockIdx.x * THREADS + threadIdx.x;
    if (b >= B) return;

    float m_sh[NSH], m_ch[NCH], m_co[NCO], m_rh[NRH], m_ro;
#pragma unroll
    for (int o = 0; o < NSH; o++) m_sh[o] = 0.0f;
#pragma unroll
    for (int o = 0; o < NCH; o++) m_ch[o] = 0.0f;
#pragma unroll
    for (int o = 0; o < NCO; o++) m_co[o] = 0.0f;
#pragma unroll
    for (int o = 0; o < NRH; o++) m_rh[o] = 0.0f;
    m_ro = 0.0f;

    const size_t TB = (size_t)TT * B;
    float* p_mco = out;                 // [T,B,3]
    float* p_sch = out + TB * 3;        // [T,B,8]
    float* p_mro = out + TB * 11;       // [T,B,1]
    float* p_srh = out + TB * 12;       // [T,B,14]
    float* p_ssh = out + TB * 26;       // [T,B,28]

    // register double-buffer for x: 32 floats = 8 float4
    float4 xc[8];
    {
        const float4* xp = (const float4*)(x + (size_t)b * NIN);
#pragma unroll
        for (int k = 0; k < 8; k++) xc[k] = __ldcs(xp + k);
    }

#pragma unroll 1
    for (int t = 0; t < TT; t++) {
        float4 xn[8];
        if (t + 1 < TT) {
            const float4* xq = (const float4*)(x + ((size_t)(t + 1) * B + b) * NIN);
#pragma unroll
            for (int k = 0; k < 8; k++) xn[k] = __ldcs(xq + k);
        }

        // ---- Layer 1: shared hidden (28 <- 32), ascending i ----
        float xs[NIN];
#pragma unroll
        for (int k = 0; k < 8; k++) {
            xs[4 * k + 0] = xc[k].x; xs[4 * k + 1] = xc[k].y;
            xs[4 * k + 2] = xc[k].z; xs[4 * k + 3] = xc[k].w;
        }
        float sps[NSH];
#pragma unroll
        for (int o = 0; o < NSH; o++) {
            float a = 0.0f;
#pragma unroll
            for (int i = 0; i < NIN; i++)
                a = __fmaf_rn(xs[i], cw[OW_SH + o * NIN + i], a);
            sps[o] = lif(m_sh[o], a + cw[OB_SH + o]);
        }
        {
            float* p = p_ssh + ((size_t)t * B + b) * NSH;
#pragma unroll
            for (int k = 0; k < 7; k++)
                __stcs((float4*)p + k,
                       make_float4(sps[4 * k], sps[4 * k + 1], sps[4 * k + 2], sps[4 * k + 3]));
        }

        // ---- Layer 2: class hidden (8 <- 28) ----
        float spc[NCH];
#pragma unroll
        for (int o = 0; o < NCH; o++)
            spc[o] = lif(m_ch[o], dot28c<OW_CH>(sps, o) + cw[OB_CH + o]);
        {
            float* p = p_sch + ((size_t)t * B + b) * NCH;
            __stcs((float4*)p,     make_float4(spc[0], spc[1], spc[2], spc[3]));
            __stcs((float4*)p + 1, make_float4(spc[4], spc[5], spc[6], spc[7]));
        }

        // ---- Layer 3: class out (3 <- 8), membrane recorded ----
        {
            float* p = p_mco + ((size_t)t * B + b) * NCO;
#pragma unroll
            for (int o = 0; o < NCO; o++) {
                float a = 0.0f;
#pragma unroll
                for (int i = 0; i < NCH; i++)
                    a = __fmaf_rn(spc[i], cw[OW_CO + o * NCH + i], a);
                (void)lif(m_co[o], a + cw[OB_CO + o]);
                __stcs(p + o, m_co[o]);
            }
        }

        // ---- Layer 4: reg hidden (14 <- 28) ----
        float spr[NRH];
#pragma unroll
        for (int o = 0; o < NRH; o++)
            spr[o] = lif(m_rh[o], dot28c<OW_RH>(sps, o) + cw[OB_RH + o]);
        {
            float* p = p_srh + ((size_t)t * B + b) * NRH;
#pragma unroll
            for (int k = 0; k < 7; k++)
                __stcs((float2*)p + k, make_float2(spr[2 * k], spr[2 * k + 1]));
        }

        // ---- Layer 5: reg out (1 <- 14), membrane recorded ----
        {
            float a = 0.0f;
#pragma unroll
            for (int i = 0; i < NRH; i++)
                a = __fmaf_rn(spr[i], cw[OW_RO + i], a);
            (void)lif(m_ro, a + cw[OB_RO]);
            __stcs(p_mro + (size_t)t * B + b, m_ro);
        }

#pragma unroll
        for (int k = 0; k < 8; k++) xc[k] = xn[k];
    }
}

extern "C" void kernel_launch(void* const* d_in, const int* in_sizes, int n_in,
                              void* d_out, int out_size) {
    const float* x   = (const float*)d_in[0];
    const float* Wsh = (const float*)d_in[1];
    const float* bsh = (const float*)d_in[2];
    const float* Wch = (const float*)d_in[3];
    const float* bch = (const float*)d_in[4];
    const float* Wco = (const float*)d_in[5];
    const float* bco = (const float*)d_in[6];
    const float* Wrh = (const float*)d_in[7];
    const float* brh = (const float*)d_in[8];
    const float* Wro = (const float*)d_in[9];
    const float* bro = (const float*)d_in[10];

    const int B = in_sizes[0] / (TT * NIN);

    // 1) pack weights into __device__ staging
    gather_kernel<<<(SW_TOTAL + 255) / 256, 256>>>(Wsh, bsh, Wch, bch, Wco, bco,
                                                   Wrh, brh, Wro, bro);
    // 2) D2D copy staging -> constant bank (capturable memcpy node)
    void* staging_addr = nullptr;
    cudaGetSymbolAddress(&staging_addr, g_staging);
    cudaMemcpyToSymbolAsync(cw, staging_addr, SW_TOTAL * sizeof(float), 0,
                            cudaMemcpyDeviceToDevice, 0);

    // 3) main kernel
    const int blocks = (B + THREADS - 1) / THREADS;
    snn_kernel<<<blocks, THREADS>>>(x, (float*)d_out, B);
}

// round 6
// speedup vs baseline: 1.0576x; 1.0576x over previous
#include <cuda_runtime.h>

// ---------------------------------------------------------------------------
// MultitaskSNN round 6: round-3 shape (1 batch/thread, 224 thr x 147 blocks,
// SMEM weights) + output-neuron-pair packing with fma.rn.f32x2.
// Each packed accumulator holds two adjacent output neurons of the SAME batch
// element; per-neuron FMA chains stay ascending-i -> bit-exact vs reference.
// Layers 2 and 4 are fused into one input loop so each spike duplication
// feeds 11 packed rows. Weights stored pre-interleaved {w[2p][i], w[2p+1][i]}.
// ---------------------------------------------------------------------------

typedef unsigned long long u64;

#define TT 50
#define NIN 32
#define THREADS 224

// u64-unit smem offsets (all even -> 16B aligned)
#define U_W1   0      // [i=32][p=14] L1 weight pairs
#define U_B1   448    // 14 bias pairs
#define U_W24  462    // [i=28][p=12] fused L2(4 pairs)+L4(7 pairs)+pad
#define U_B24  798    // 12 bias pairs (11 used)
// float-unit offsets (u64 region ends at 810 -> float 1620)
#define F_W3   1620   // [3][8] class-out weights (rows 16B aligned)
#define F_B3   1644   // 3
#define F_W5   1648   // 14 reg-out weights (16B aligned)
#define F_B5   1662   // 1
#define SW_FLOATS 1664

__device__ __forceinline__ u64 pack2(float lo, float hi) {
    u64 r; asm("mov.b64 %0, {%1, %2};" : "=l"(r) : "f"(lo), "f"(hi)); return r;
}
__device__ __forceinline__ void unpack2(u64 v, float& lo, float& hi) {
    asm("mov.b64 {%0, %1}, %2;" : "=f"(lo), "=f"(hi) : "l"(v));
}
__device__ __forceinline__ u64 fma2(u64 a, u64 b, u64 c) {
    u64 d; asm("fma.rn.f32x2 %0, %1, %2, %3;" : "=l"(d) : "l"(a), "l"(b), "l"(c)); return d;
}
__device__ __forceinline__ u64 add2(u64 a, u64 b) {
    u64 d; asm("add.rn.f32x2 %0, %1, %2;" : "=l"(d) : "l"(a), "l"(b)); return d;
}

#define BETA2 0x3F6666663F666666ull  // {0.9f, 0.9f}

// packed LIF; per-lane bits identical to: r=(m>1); m=fma(0.9,m,cur)-r; s=(m>1)
__device__ __forceinline__ u64 lif2(u64& m2, u64 cur2) {
    float m0, m1;
    unpack2(m2, m0, m1);
    float r0 = (m0 > 1.0f) ? -1.0f : 0.0f;
    float r1 = (m1 > 1.0f) ? -1.0f : 0.0f;
    m2 = add2(fma2(BETA2, m2, cur2), pack2(r0, r1));
    float n0, n1;
    unpack2(m2, n0, n1);
    return pack2((n0 > 1.0f) ? 1.0f : 0.0f, (n1 > 1.0f) ? 1.0f : 0.0f);
}

// scalar LIF (layers 3/5), identical rounding
__device__ __forceinline__ float lif(float& m, float cur) {
    float r = (m > 1.0f) ? 1.0f : 0.0f;
    m = __fmaf_rn(0.9f, m, cur) - r;
    return (m > 1.0f) ? 1.0f : 0.0f;
}

__global__ __launch_bounds__(THREADS, 1) void snn_kernel(
    const float* __restrict__ x,
    const float* __restrict__ Wsh, const float* __restrict__ bsh,
    const float* __restrict__ Wch, const float* __restrict__ bch,
    const float* __restrict__ Wco, const float* __restrict__ bco,
    const float* __restrict__ Wrh, const float* __restrict__ brh,
    const float* __restrict__ Wro, const float* __restrict__ bro,
    float* __restrict__ out, int B)
{
    __shared__ __align__(16) float swf[SW_FLOATS];
    u64* swu = (u64*)swf;
    const int tid = threadIdx.x;

    for (int i = tid; i < SW_FLOATS; i += THREADS) swf[i] = 0.0f;
    __syncthreads();

    // L1 weight pairs: swu[U_W1 + i*14 + p] = {Wsh[2p][i], Wsh[2p+1][i]}
    for (int idx = tid; idx < 32 * 14; idx += THREADS) {
        int i = idx / 14, p = idx % 14;
        int u = U_W1 + idx;
        swf[2 * u + 0] = Wsh[(2 * p) * NIN + i];
        swf[2 * u + 1] = Wsh[(2 * p + 1) * NIN + i];
    }
    for (int p = tid; p < 14; p += THREADS) {
        swf[2 * (U_B1 + p) + 0] = bsh[2 * p];
        swf[2 * (U_B1 + p) + 1] = bsh[2 * p + 1];
    }
    // fused L2+L4 pairs: p 0..3 = class hidden, p 4..10 = reg hidden, p 11 pad
    for (int idx = tid; idx < 28 * 11; idx += THREADS) {
        int i = idx / 11, p = idx % 11;
        int u = U_W24 + i * 12 + p;
        if (p < 4) {
            swf[2 * u + 0] = Wch[(2 * p) * 28 + i];
            swf[2 * u + 1] = Wch[(2 * p + 1) * 28 + i];
        } else {
            int q = p - 4;
            swf[2 * u + 0] = Wrh[(2 * q) * 28 + i];
            swf[2 * u + 1] = Wrh[(2 * q + 1) * 28 + i];
        }
    }
    for (int p = tid; p < 11; p += THREADS) {
        if (p < 4) {
            swf[2 * (U_B24 + p) + 0] = bch[2 * p];
            swf[2 * (U_B24 + p) + 1] = bch[2 * p + 1];
        } else {
            int q = p - 4;
            swf[2 * (U_B24 + p) + 0] = brh[2 * q];
            swf[2 * (U_B24 + p) + 1] = brh[2 * q + 1];
        }
    }
    for (int i = tid; i < 24; i += THREADS) swf[F_W3 + i] = Wco[i];
    for (int i = tid; i < 3;  i += THREADS) swf[F_B3 + i] = bco[i];
    for (int i = tid; i < 14; i += THREADS) swf[F_W5 + i] = Wro[i];
    if (tid == 0) swf[F_B5] = bro[0];
    __syncthreads();

    const int b = blockIdx.x * THREADS + tid;
    if (b >= B) return;

    u64 m_sh[14], m_bh[11];
    float m_co[3], m_ro = 0.0f;
#pragma unroll
    for (int p = 0; p < 14; p++) m_sh[p] = 0ull;
#pragma unroll
    for (int p = 0; p < 11; p++) m_bh[p] = 0ull;
#pragma unroll
    for (int o = 0; o < 3; o++) m_co[o] = 0.0f;

    const size_t TB = (size_t)TT * B;
    float* p_mco = out;                 // [T,B,3]
    float* p_sch = out + TB * 3;        // [T,B,8]
    float* p_mro = out + TB * 11;       // [T,B,1]
    float* p_srh = out + TB * 12;       // [T,B,14]
    float* p_ssh = out + TB * 26;       // [T,B,28]

    // x register double buffer
    float4 xc[8];
    {
        const float4* xp = (const float4*)(x + (size_t)b * NIN);
#pragma unroll
        for (int k = 0; k < 8; k++) xc[k] = __ldcs(xp + k);
    }

#pragma unroll 1
    for (int t = 0; t < TT; t++) {
        // prefetch next x (clamped index; value discarded on last step)
        float4 xn[8];
        {
            const int tn = (t + 1 < TT) ? t + 1 : t;
            const float4* xq = (const float4*)(x + ((size_t)tn * B + b) * NIN);
#pragma unroll
            for (int k = 0; k < 8; k++) xn[k] = __ldcs(xq + k);
        }

        // ---- Layer 1: 14 output pairs <- 32 inputs ----
        u64 acc[14];
#pragma unroll
        for (int p = 0; p < 14; p++) acc[p] = 0ull;
#pragma unroll
        for (int k = 0; k < 8; k++) {
            const float xv[4] = {xc[k].x, xc[k].y, xc[k].z, xc[k].w};
#pragma unroll
            for (int j = 0; j < 4; j++) {
                u64 d = pack2(xv[j], xv[j]);
                const u64* w = swu + U_W1 + (4 * k + j) * 14;
#pragma unroll
                for (int pp = 0; pp < 7; pp++) {
                    ulonglong2 wp = *(const ulonglong2*)(w + 2 * pp);
                    acc[2 * pp]     = fma2(d, wp.x, acc[2 * pp]);
                    acc[2 * pp + 1] = fma2(d, wp.y, acc[2 * pp + 1]);
                }
            }
        }
        u64 sps[14];
#pragma unroll
        for (int p = 0; p < 14; p++)
            sps[p] = lif2(m_sh[p], add2(acc[p], swu[U_B1 + p]));

        // store spk_sh: 28 floats (16B-aligned base)
        {
            float* p = p_ssh + ((size_t)t * B + b) * 28;
#pragma unroll
            for (int k = 0; k < 7; k++) {
                float a, bb, c, dd;
                unpack2(sps[2 * k], a, bb);
                unpack2(sps[2 * k + 1], c, dd);
                __stcs((float4*)p + k, make_float4(a, bb, c, dd));
            }
        }

        // ---- fused Layers 2+4: 11 output pairs <- 28 spikes ----
        u64 a2[11];
#pragma unroll
        for (int p = 0; p < 11; p++) a2[p] = 0ull;
#pragma unroll
        for (int q = 0; q < 14; q++) {
            float s0, s1;
            unpack2(sps[q], s0, s1);
            // input i = 2q
            {
                u64 d = pack2(s0, s0);
                const u64* w = swu + U_W24 + (2 * q) * 12;
#pragma unroll
                for (int pp = 0; pp < 5; pp++) {
                    ulonglong2 wp = *(const ulonglong2*)(w + 2 * pp);
                    a2[2 * pp]     = fma2(d, wp.x, a2[2 * pp]);
                    a2[2 * pp + 1] = fma2(d, wp.y, a2[2 * pp + 1]);
                }
                ulonglong2 wp = *(const ulonglong2*)(w + 10);
                a2[10] = fma2(d, wp.x, a2[10]);
            }
            // input i = 2q+1
            {
                u64 d = pack2(s1, s1);
                const u64* w = swu + U_W24 + (2 * q + 1) * 12;
#pragma unroll
                for (int pp = 0; pp < 5; pp++) {
                    ulonglong2 wp = *(const ulonglong2*)(w + 2 * pp);
                    a2[2 * pp]     = fma2(d, wp.x, a2[2 * pp]);
                    a2[2 * pp + 1] = fma2(d, wp.y, a2[2 * pp + 1]);
                }
                ulonglong2 wp = *(const ulonglong2*)(w + 10);
                a2[10] = fma2(d, wp.x, a2[10]);
            }
        }
        u64 spc[4], spr[7];
#pragma unroll
        for (int p = 0; p < 4; p++)
            spc[p] = lif2(m_bh[p], add2(a2[p], swu[U_B24 + p]));
#pragma unroll
        for (int p = 0; p < 7; p++)
            spr[p] = lif2(m_bh[4 + p], add2(a2[4 + p], swu[U_B24 + 4 + p]));

        // store spk_ch (8 floats) and spk_rh (14 floats)
        {
            float* p = p_sch + ((size_t)t * B + b) * 8;
            float a, bb, c, dd, e, f, g, h;
            unpack2(spc[0], a, bb); unpack2(spc[1], c, dd);
            unpack2(spc[2], e, f);  unpack2(spc[3], g, h);
            __stcs((float4*)p,     make_float4(a, bb, c, dd));
            __stcs((float4*)p + 1, make_float4(e, f, g, h));
        }
        {
            float* p = p_srh + ((size_t)t * B + b) * 14;
#pragma unroll
            for (int k = 0; k < 7; k++) {
                float a, bb;
                unpack2(spr[k], a, bb);
                __stcs((float2*)p + k, make_float2(a, bb));
            }
        }

        // ---- Layer 3: class out (3 <- 8), scalar ----
        {
            float c[8];
            unpack2(spc[0], c[0], c[1]); unpack2(spc[1], c[2], c[3]);
            unpack2(spc[2], c[4], c[5]); unpack2(spc[3], c[6], c[7]);
            float* p = p_mco + ((size_t)t * B + b) * 3;
#pragma unroll
            for (int o = 0; o < 3; o++) {
                float4 w0 = *(const float4*)(swf + F_W3 + o * 8);
                float4 w1 = *(const float4*)(swf + F_W3 + o * 8 + 4);
                float a = 0.0f;
                a = __fmaf_rn(c[0], w0.x, a);
                a = __fmaf_rn(c[1], w0.y, a);
                a = __fmaf_rn(c[2], w0.z, a);
                a = __fmaf_rn(c[3], w0.w, a);
                a = __fmaf_rn(c[4], w1.x, a);
                a = __fmaf_rn(c[5], w1.y, a);
                a = __fmaf_rn(c[6], w1.z, a);
                a = __fmaf_rn(c[7], w1.w, a);
                (void)lif(m_co[o], a + swf[F_B3 + o]);
                __stcs(p + o, m_co[o]);
            }
        }

        // ---- Layer 5: reg out (1 <- 14), scalar ----
        {
            float r[14];
#pragma unroll
            for (int k = 0; k < 7; k++) unpack2(spr[k], r[2 * k], r[2 * k + 1]);
            float4 w0 = *(const float4*)(swf + F_W5);
            float4 w1 = *(const float4*)(swf + F_W5 + 4);
            float4 w2 = *(const float4*)(swf + F_W5 + 8);
            float2 w3 = *(const float2*)(swf + F_W5 + 12);
            float a = 0.0f;
            a = __fmaf_rn(r[0],  w0.x, a);
            a = __fmaf_rn(r[1],  w0.y, a);
            a = __fmaf_rn(r[2],  w0.z, a);
            a = __fmaf_rn(r[3],  w0.w, a);
            a = __fmaf_rn(r[4],  w1.x, a);
            a = __fmaf_rn(r[5],  w1.y, a);
            a = __fmaf_rn(r[6],  w1.z, a);
            a = __fmaf_rn(r[7],  w1.w, a);
            a = __fmaf_rn(r[8],  w2.x, a);
            a = __fmaf_rn(r[9],  w2.y, a);
            a = __fmaf_rn(r[10], w2.z, a);
            a = __fmaf_rn(r[11], w2.w, a);
            a = __fmaf_rn(r[12], w3.x, a);
            a = __fmaf_rn(r[13], w3.y, a);
            (void)lif(m_ro, a + swf[F_B5]);
            __stcs(p_mro + (size_t)t * B + b, m_ro);
        }

        // rotate x buffer
#pragma unroll
        for (int k = 0; k < 8; k++) xc[k] = xn[k];
    }
}

extern "C" void kernel_launch(void* const* d_in, const int* in_sizes, int n_in,
                              void* d_out, int out_size) {
    const float* x   = (const float*)d_in[0];
    const float* Wsh = (const float*)d_in[1];
    const float* bsh = (const float*)d_in[2];
    const float* Wch = (const float*)d_in[3];
    const float* bch = (const float*)d_in[4];
    const float* Wco = (const float*)d_in[5];
    const float* bco = (const float*)d_in[6];
    const float* Wrh = (const float*)d_in[7];
    const float* brh = (const float*)d_in[8];
    const float* Wro = (const float*)d_in[9];
    const float* bro = (const float*)d_in[10];

    const int B = in_sizes[0] / (TT * NIN);
    const int blocks = (B + THREADS - 1) / THREADS;

    snn_kernel<<<blocks, THREADS>>>(x, Wsh, bsh, Wch, bch, Wco, bco,
                                    Wrh, brh, Wro, bro, (float*)d_out, B);
}